// round 12
// baseline (speedup 1.0000x reference)
#include <cuda_runtime.h>
#include <cuda_fp16.h>
#include <cstdint>

// NearestNeighborGraph: 16 samples x 2048 points x 64 dims, K=16.
// Output (float32): [knn_dist | dst | src], each 16*2048*16.
//
// fp16 2-term-split mma.sync Gram half-tiles; distances staged in one SMEM
// half-buffer; warp-cooperative top-16 selection: each row's sorted top-16
// lives distributed across lanes 0..15 (keys in SMEM), gate threshold is
// warp-uniform (lane 15), inserts are warp-uniform shfl shifts.

#define NS     16
#define NP     2048
#define DIMS   64
#define KNN    16
#define TM     128
#define TN     128
#define NTILES (NP / TN)
#define OUTBLK (NS * NP * KNN)

#define PITCHB 144           // B smem row pitch bytes (9x16B, ldmatrix conflict-free)
#define PITCHQ 9             // uint4 per row
#define TILEQ  (TM * PITCHQ) // 1152 uint4 = 18432 B per term plane
#define DPITCH 68            // dist half-tile row pitch in floats (64+4)

// SMEM layout (bytes)
#define SM_B   0             // hi plane at +0, lo plane at +SM_LO
#define SM_LO  18432
#define SM_D   36864         // 128*68*4 = 34816
#define SM_KEY 71680         // 128 rows * 16 * 8B = 16384
#define SM_CN  88064         // 512
#define SM_TOT 88576

__device__ uint4 g_h16[NS * NP * PITCHQ];  // fp16 hi plane, 144B pitch
__device__ uint4 g_l16[NS * NP * PITCHQ];  // fp16 lo plane
__device__ float g_x2[NS * NP];            // fp32 norms

// ---------------- helpers ----------------
__device__ __forceinline__ uint32_t smem_u32(const void* p) {
    uint32_t a;
    asm("{ .reg .u64 t; cvta.to.shared.u64 t, %1; cvt.u32.u64 %0, t; }"
        : "=r"(a) : "l"(p));
    return a;
}

__device__ __forceinline__ void ldsm4(uint32_t* r, uint32_t addr) {
    asm volatile("ldmatrix.sync.aligned.m8n8.x4.shared.b16 {%0,%1,%2,%3}, [%4];"
                 : "=r"(r[0]), "=r"(r[1]), "=r"(r[2]), "=r"(r[3]) : "r"(addr));
}

__device__ __forceinline__ void mma16816(float* d, const uint32_t* a,
                                         const uint32_t* b) {
    asm volatile(
        "mma.sync.aligned.m16n8k16.row.col.f32.f16.f16.f32 "
        "{%0,%1,%2,%3}, {%4,%5,%6,%7}, {%8,%9}, {%0,%1,%2,%3};"
        : "+f"(d[0]), "+f"(d[1]), "+f"(d[2]), "+f"(d[3])
        : "r"(a[0]), "r"(a[1]), "r"(a[2]), "r"(a[3]), "r"(b[0]), "r"(b[1]));
}

__device__ __forceinline__ void cp16(uint32_t saddr, const void* gaddr) {
    asm volatile("cp.async.cg.shared.global [%0], [%1], 16;"
                 :: "r"(saddr), "l"(gaddr));
}
__device__ __forceinline__ void cp4(uint32_t saddr, const void* gaddr) {
    asm volatile("cp.async.ca.shared.global [%0], [%1], 4;"
                 :: "r"(saddr), "l"(gaddr));
}
#define CP_COMMIT() asm volatile("cp.async.commit_group;" ::: "memory")
#define CP_WAIT0()  asm volatile("cp.async.wait_group 0;" ::: "memory")

__device__ __forceinline__ uint32_t pack_h2(__half lo, __half hi) {
    __half2 h = __halves2half2(lo, hi);
    return *reinterpret_cast<uint32_t*>(&h);
}

// order-preserving float->u32 transform (u-compare == f-compare)
__device__ __forceinline__ uint32_t ordf(float f) {
    uint32_t u = __float_as_uint(f);
    return u ^ ((uint32_t)((int)u >> 31) | 0x80000000u);
}

// ---------------- prologue: fp16 split planes + norms ----------------
__global__ void __launch_bounds__(256) prep_kernel(const float* __restrict__ h) {
    int r = blockIdx.x * blockDim.x + threadIdx.x;
    if (r >= NS * NP) return;
    const float4* src = reinterpret_cast<const float4*>(h + (size_t)r * DIMS);
    float s = 0.f;
#pragma unroll
    for (int q = 0; q < 8; ++q) {
        float4 x0 = src[2 * q];
        float4 x1 = src[2 * q + 1];
        float f[8] = {x0.x, x0.y, x0.z, x0.w, x1.x, x1.y, x1.z, x1.w};
        uint32_t rh[4], rl[4];
#pragma unroll
        for (int e = 0; e < 4; ++e) {
            float a = f[2 * e], c = f[2 * e + 1];
            __half ah = __float2half_rn(a), ch = __float2half_rn(c);
            float al = a - __half2float(ah);
            float cl = c - __half2float(ch);
            rh[e] = pack_h2(ah, ch);
            rl[e] = pack_h2(__float2half_rn(al), __float2half_rn(cl));
            s += a * a;
            s += c * c;
        }
        g_h16[(size_t)r * PITCHQ + q] = make_uint4(rh[0], rh[1], rh[2], rh[3]);
        g_l16[(size_t)r * PITCHQ + q] = make_uint4(rl[0], rl[1], rl[2], rl[3]);
    }
    g_h16[(size_t)r * PITCHQ + 8] = make_uint4(0, 0, 0, 0);
    g_l16[(size_t)r * PITCHQ + 8] = make_uint4(0, 0, 0, 0);
    g_x2[r] = s;
}

// ---- compute one 64-col half: MMA + fold + store to D ----
__device__ __forceinline__ void compute_half(
    uint32_t sbB, uint32_t b_lane_off, int h,
    const uint32_t Ah[4][4], const uint32_t Al[4][4],
    float* distf, const float* cn, int row0, int tg, float qn0, float qn1) {
    float acc[8][4];
#pragma unroll
    for (int nt = 0; nt < 8; ++nt)
#pragma unroll
        for (int e = 0; e < 4; ++e) acc[nt][e] = 0.f;
#pragma unroll
    for (int np = 0; np < 4; ++np) {
#pragma unroll
        for (int k = 0; k < 4; ++k) {
            uint32_t Bh[4], Bl[4];
            uint32_t ba = sbB + b_lane_off +
                          (uint32_t)((h * 64 + np * 16) * PITCHB) +
                          (uint32_t)(k * 32);
            ldsm4(Bh, ba);
            ldsm4(Bl, ba + SM_LO);
            mma16816(acc[2 * np],     Ah[k], Bh + 0);
            mma16816(acc[2 * np],     Ah[k], Bl + 0);
            mma16816(acc[2 * np],     Al[k], Bh + 0);
            mma16816(acc[2 * np + 1], Ah[k], Bh + 2);
            mma16816(acc[2 * np + 1], Ah[k], Bl + 2);
            mma16816(acc[2 * np + 1], Al[k], Bh + 2);
        }
    }
#pragma unroll
    for (int nt = 0; nt < 8; ++nt) {
        const int c0 = nt * 8 + tg * 2;
        float2 cnp = *reinterpret_cast<const float2*>(cn + h * 64 + c0);
        float2 d0, d1;
        d0.x = fmaf(-2.f, acc[nt][0], qn0 + cnp.x);
        d0.y = fmaf(-2.f, acc[nt][1], qn0 + cnp.y);
        d1.x = fmaf(-2.f, acc[nt][2], qn1 + cnp.x);
        d1.y = fmaf(-2.f, acc[nt][3], qn1 + cnp.y);
        *reinterpret_cast<float2*>(distf + (size_t)row0 * DPITCH + c0) = d0;
        *reinterpret_cast<float2*>(distf + (size_t)(row0 + 8) * DPITCH + c0) = d1;
    }
}

// ---- warp-cooperative selection over one 64-col half ----
// Row's sorted top-16 distributed across lanes 0..15 (SMEM), kv = {idx, ord}.
__device__ __forceinline__ void select_half(
    uint2* keys, const float* distf, int w, int lane, int baseidx) {
    const unsigned FULL = 0xFFFFFFFFu;
#pragma unroll 1
    for (int r = 0; r < 16; ++r) {
        const int row = w * 16 + r;
        uint2 kv = keys[row * 16 + (lane & 15)];
        uint32_t thr = __shfl_sync(FULL, kv.y, 15);
        float2 v = *reinterpret_cast<const float2*>(
            distf + (size_t)row * DPITCH + lane * 2);
        uint32_t u0 = ordf(v.x), u1 = ordf(v.y);
        bool chg = false;
#pragma unroll 1
        for (int j = 0; j < 2; ++j) {
            uint32_t uj = j ? u1 : u0;
            uint32_t bal = __ballot_sync(FULL, uj < thr);
            while (bal) {
                int src = __ffs(bal) - 1;
                bal &= bal - 1;
                uint32_t kn_h = __shfl_sync(FULL, uj, src);
                if (kn_h >= thr) continue;  // stale after prior insert
                uint32_t kn_l = (uint32_t)(baseidx + 2 * src + j);
                // insertion position among lanes 0..15 (keys ascending)
                bool p = (lane < 16) &&
                         (kv.y > kn_h || (kv.y == kn_h && kv.x > kn_l));
                uint32_t bi = __ballot_sync(FULL, p);
                int pos = __ffs(bi) - 1;  // bi!=0: lane15 key > kn guaranteed
                uint32_t sh_y = __shfl_up_sync(FULL, kv.y, 1);
                uint32_t sh_x = __shfl_up_sync(FULL, kv.x, 1);
                if (lane > pos)       { kv.y = sh_y; kv.x = sh_x; }
                else if (lane == pos) { kv.y = kn_h; kv.x = kn_l; }
                thr = __shfl_sync(FULL, kv.y, 15);
                chg = true;
            }
        }
        if (chg && lane < 16) keys[row * 16 + lane] = kv;
    }
}

// ---------------- main kernel ----------------
__global__ void __launch_bounds__(256, 2) knn_kernel(float* __restrict__ out,
                                                     int write_edges) {
    extern __shared__ char smem[];
    const uint32_t sb = smem_u32(smem);
    const int tid  = threadIdx.x;
    const int w    = tid >> 5;
    const int lane = tid & 31;
    const int tg   = lane & 3;
    const int g    = lane >> 2;
    const int b    = blockIdx.y;
    const int qbase = blockIdx.x * TM;

    uint2* keys  = reinterpret_cast<uint2*>(smem + SM_KEY);
    float* distf = reinterpret_cast<float*>(smem + SM_D);

    // ---- init keys (+inf sentinels) ----
#pragma unroll
    for (int i = 0; i < 8; ++i)
        keys[tid + i * 256] = make_uint2(0xFFFFFFFFu, 0xFFFFFFFFu);

    // ---- stage A (query) planes into the B region (dead after frag load) ----
    {
        const uint4* srcH = g_h16 + (size_t)(b * NP + qbase) * PITCHQ;
        const uint4* srcL = g_l16 + (size_t)(b * NP + qbase) * PITCHQ;
        uint4* dA = reinterpret_cast<uint4*>(smem + SM_B);
        for (int i = tid; i < TILEQ; i += 256) {
            dA[i]         = srcH[i];
            dA[TILEQ + i] = srcL[i];
        }
    }
    __syncthreads();

    // ---- cache A fragments ----
    uint32_t Ah[4][4], Al[4][4];
    {
        uint32_t a_off = sb + SM_B + (uint32_t)(w * 16 + (lane & 15)) * PITCHB +
                         (uint32_t)(lane >> 4) * 16;
#pragma unroll
        for (int k = 0; k < 4; ++k) {
            ldsm4(Ah[k], a_off + k * 32);
            ldsm4(Al[k], a_off + SM_LO + k * 32);
        }
    }
    const int row0 = w * 16 + g;
    const float qn0 = g_x2[b * NP + qbase + row0];
    const float qn1 = g_x2[b * NP + qbase + row0 + 8];

    const uint32_t b_lane_off =
        (uint32_t)(((lane & 7) + ((lane >> 4) << 3)) * PITCHB) +
        ((lane & 8) ? 16u : 0u);
    const float* cn = reinterpret_cast<const float*>(smem + SM_CN);

    __syncthreads();  // frags read -> B region reusable

    // ---- preload tile 0 ----
    {
        const uint4* sH = g_h16 + (size_t)(b * NP) * PITCHQ;
        const uint4* sL = g_l16 + (size_t)(b * NP) * PITCHQ;
        for (int i = tid; i < TILEQ; i += 256) {
            cp16(sb + SM_B + i * 16,         sH + i);
            cp16(sb + SM_B + SM_LO + i * 16, sL + i);
        }
        if (tid < TN) cp4(sb + SM_CN + tid * 4, g_x2 + b * NP + tid);
        CP_COMMIT();
        CP_WAIT0();
    }
    __syncthreads();

    for (int tt = 0; tt < NTILES; ++tt) {
        // -- half 0: compute -> select --
        compute_half(sb + SM_B, b_lane_off, 0, Ah, Al, distf, cn, row0, tg,
                     qn0, qn1);
        __syncthreads();  // D(h0) ready
        select_half(keys, distf, w, lane, tt * TN + 0);
        __syncthreads();  // D reusable

        // -- half 1: compute (last B use) --
        compute_half(sb + SM_B, b_lane_off, 1, Ah, Al, distf, cn, row0, tg,
                     qn0, qn1);
        __syncthreads();  // D(h1) ready; all warps done reading B

        // -- prefetch tile tt+1 into B (overlaps select h1) --
        if (tt + 1 < NTILES) {
            const uint4* sH = g_h16 + (size_t)(b * NP + (tt + 1) * TN) * PITCHQ;
            const uint4* sL = g_l16 + (size_t)(b * NP + (tt + 1) * TN) * PITCHQ;
            for (int i = tid; i < TILEQ; i += 256) {
                cp16(sb + SM_B + i * 16,         sH + i);
                cp16(sb + SM_B + SM_LO + i * 16, sL + i);
            }
            if (tid < TN)
                cp4(sb + SM_CN + tid * 4, g_x2 + b * NP + (tt + 1) * TN + tid);
        }
        CP_COMMIT();

        select_half(keys, distf, w, lane, tt * TN + 64);
        CP_WAIT0();
        __syncthreads();  // next B visible; D free
    }

    // ---- emit: thread r writes row r's 16 results ----
    if (tid < TM) {
        const int r   = tid;
        const int gqi = b * NP + qbase + r;
        float* od   = out + (size_t)gqi * KNN;
        float* odst = out + OUTBLK + (size_t)gqi * KNN;
        float* osrc = out + 2 * OUTBLK + (size_t)gqi * KNN;
        const float fsrc = (float)gqi;
#pragma unroll
        for (int k = 0; k < KNN; ++k) {
            uint2 kv = keys[r * 16 + k];
            uint32_t o = kv.y;
            uint32_t msk = (o & 0x80000000u) ? 0x80000000u : 0xFFFFFFFFu;
            od[k] = __uint_as_float(o ^ msk);
            if (write_edges) {
                odst[k] = (float)(kv.x + (uint32_t)(b * NP));
                osrc[k] = fsrc;
            }
        }
    }
}

extern "C" void kernel_launch(void* const* d_in, const int* in_sizes, int n_in,
                              void* d_out, int out_size) {
    const float* h   = (const float*)d_in[0];
    float*       out = (float*)d_out;
    const int write_edges = (out_size >= 3 * OUTBLK) ? 1 : 0;

    cudaFuncSetAttribute(knn_kernel, cudaFuncAttributeMaxDynamicSharedMemorySize,
                         SM_TOT);

    prep_kernel<<<(NS * NP) / 256, 256>>>(h);
    dim3 grid(NP / TM, NS);
    knn_kernel<<<grid, 256, SM_TOT>>>(out, write_edges);
}

// round 14
// speedup vs baseline: 2.1503x; 2.1503x over previous
#include <cuda_runtime.h>
#include <cuda_fp16.h>
#include <cstdint>

// NearestNeighborGraph: 16 samples x 2048 points x 64 dims, K=16.
// Output (float32): [knn_dist | dst | src], each 16*2048*16.
//
// fp16 2-term-split mma.sync Gram tiles; distances staged in two SMEM
// half-buffers; selection = branchless pass-mask build + compact ffs-driven
// insert loop into per-thread sorted top-16 lists. 2 CTAs/SM.

#define NS     16
#define NP     2048
#define DIMS   64
#define KNN    16
#define TM     128
#define TN     128
#define NTILES (NP / TN)
#define OUTBLK (NS * NP * KNN)

#define PITCHB 144           // A/B smem row pitch bytes (9x16B, ldmatrix conflict-free)
#define PITCHQ 9             // uint4 per row
#define TILEQ  (TM * PITCHQ) // 1152 uint4 = 18432 B per term tile
#define DPITCH 68            // dist half-tile row pitch in floats (64+4)

// SMEM layout (bytes). A staged in B region pre-loop (dead after frag load).
#define SM_B   0
#define SM_BH  0
#define SM_BL  18432
#define SM_D0  36864
#define SM_D1  (SM_D0 + TM * DPITCH * 4)   // 71680
#define SM_CN  (SM_D1 + TM * DPITCH * 4)   // 106496
#define SM_TOT (SM_CN + 512)               // 107008

__device__ uint4 g_h16[NS * NP * PITCHQ];  // fp16 hi plane, 144B pitch
__device__ uint4 g_l16[NS * NP * PITCHQ];  // fp16 lo plane
__device__ float g_x2[NS * NP];            // fp32 norms

// ---------------- helpers ----------------
__device__ __forceinline__ uint32_t smem_u32(const void* p) {
    uint32_t a;
    asm("{ .reg .u64 t; cvta.to.shared.u64 t, %1; cvt.u32.u64 %0, t; }"
        : "=r"(a) : "l"(p));
    return a;
}

__device__ __forceinline__ void ldsm4(uint32_t* r, uint32_t addr) {
    asm volatile("ldmatrix.sync.aligned.m8n8.x4.shared.b16 {%0,%1,%2,%3}, [%4];"
                 : "=r"(r[0]), "=r"(r[1]), "=r"(r[2]), "=r"(r[3]) : "r"(addr));
}

__device__ __forceinline__ void mma16816(float* d, const uint32_t* a,
                                         const uint32_t* b) {
    asm volatile(
        "mma.sync.aligned.m16n8k16.row.col.f32.f16.f16.f32 "
        "{%0,%1,%2,%3}, {%4,%5,%6,%7}, {%8,%9}, {%0,%1,%2,%3};"
        : "+f"(d[0]), "+f"(d[1]), "+f"(d[2]), "+f"(d[3])
        : "r"(a[0]), "r"(a[1]), "r"(a[2]), "r"(a[3]), "r"(b[0]), "r"(b[1]));
}

__device__ __forceinline__ uint32_t pack_h2(__half lo, __half hi) {
    __half2 h = __halves2half2(lo, hi);
    return *reinterpret_cast<uint32_t*>(&h);
}

// Float sorted insert; strict '<' + ascending idx processing order => stable
// ties toward the smaller index (lax.top_k semantics).
#define INSERTF(dval, idx) do {                                                \
    if ((dval) < dk[KNN - 1]) {                                                \
        dk[KNN - 1] = (dval);                                                  \
        ik[KNN - 1] = (idx);                                                   \
        _Pragma("unroll")                                                      \
        for (int _t = KNN - 1; _t > 0; --_t) {                                 \
            if (dk[_t] < dk[_t - 1]) {                                         \
                float _fd = dk[_t]; dk[_t] = dk[_t - 1]; dk[_t - 1] = _fd;     \
                int   _fi = ik[_t]; ik[_t] = ik[_t - 1]; ik[_t - 1] = _fi;     \
            }                                                                  \
        }                                                                      \
    }                                                                          \
} while (0)

// ---------------- prologue: fp16 split planes + norms ----------------
__global__ void __launch_bounds__(256) prep_kernel(const float* __restrict__ h) {
    int r = blockIdx.x * blockDim.x + threadIdx.x;
    if (r >= NS * NP) return;
    const float4* src = reinterpret_cast<const float4*>(h + (size_t)r * DIMS);
    float s = 0.f;
#pragma unroll
    for (int q = 0; q < 8; ++q) {
        float4 x0 = src[2 * q];
        float4 x1 = src[2 * q + 1];
        float f[8] = {x0.x, x0.y, x0.z, x0.w, x1.x, x1.y, x1.z, x1.w};
        uint32_t rh[4], rl[4];
#pragma unroll
        for (int e = 0; e < 4; ++e) {
            float a = f[2 * e], c = f[2 * e + 1];
            __half ah = __float2half_rn(a), ch = __float2half_rn(c);
            float al = a - __half2float(ah);
            float cl = c - __half2float(ch);
            rh[e] = pack_h2(ah, ch);
            rl[e] = pack_h2(__float2half_rn(al), __float2half_rn(cl));
            s += a * a;
            s += c * c;
        }
        g_h16[(size_t)r * PITCHQ + q] = make_uint4(rh[0], rh[1], rh[2], rh[3]);
        g_l16[(size_t)r * PITCHQ + q] = make_uint4(rl[0], rl[1], rl[2], rl[3]);
    }
    g_h16[(size_t)r * PITCHQ + 8] = make_uint4(0, 0, 0, 0);
    g_l16[(size_t)r * PITCHQ + 8] = make_uint4(0, 0, 0, 0);
    g_x2[r] = s;
}

// ---------------- main kernel ----------------
__global__ void __launch_bounds__(256, 2) knn_kernel(float* __restrict__ out,
                                                     int write_edges) {
    extern __shared__ char smem[];
    const uint32_t sb = smem_u32(smem);
    const int tid  = threadIdx.x;
    const int w    = tid >> 5;
    const int lane = tid & 31;
    const int tg   = lane & 3;
    const int g    = lane >> 2;
    const int b    = blockIdx.y;
    const int qbase = blockIdx.x * TM;

    // ---- stage A (query) tiles into the B region (dead after frag load) ----
    {
        const uint4* srcH = g_h16 + (size_t)(b * NP + qbase) * PITCHQ;
        const uint4* srcL = g_l16 + (size_t)(b * NP + qbase) * PITCHQ;
        uint4* dA = reinterpret_cast<uint4*>(smem + SM_B);
        for (int i = tid; i < TILEQ; i += 256) {
            dA[i]         = srcH[i];
            dA[TILEQ + i] = srcL[i];
        }
    }
    __syncthreads();

    // ---- cache A fragments (fixed for whole CTA) ----
    uint32_t Ah[4][4], Al[4][4];
    {
        uint32_t a_off = sb + SM_BH + (uint32_t)(w * 16 + (lane & 15)) * PITCHB +
                         (uint32_t)(lane >> 4) * 16;
#pragma unroll
        for (int k = 0; k < 4; ++k) {
            ldsm4(Ah[k], a_off + k * 32);
            ldsm4(Al[k], a_off + (SM_BL - SM_BH) + k * 32);
        }
    }
    const int row0 = w * 16 + g;
    const float qn0 = g_x2[b * NP + qbase + row0];
    const float qn1 = g_x2[b * NP + qbase + row0 + 8];

    // ---- scan thread state: half a row each ----
    const int srow = tid >> 1;
    const int shb  = tid & 1;
    float dk[KNN];
    int   ik[KNN];
#pragma unroll
    for (int k = 0; k < KNN; ++k) { dk[k] = 3.4e38f; ik[k] = 0; }

    const uint32_t b_lane_off =
        (uint32_t)(((lane & 7) + ((lane >> 4) << 3)) * PITCHB) +
        ((lane & 8) ? 16u : 0u);
    const float* cn = reinterpret_cast<const float*>(smem + SM_CN);

    for (int tt = 0; tt < NTILES; ++tt) {
        __syncthreads();  // prev tile scan + A-frag load done: B region reusable
        {
            const uint4* sH = g_h16 + (size_t)(b * NP + tt * TN) * PITCHQ;
            const uint4* sL = g_l16 + (size_t)(b * NP + tt * TN) * PITCHQ;
            uint4* dB = reinterpret_cast<uint4*>(smem + SM_B);
            for (int i = tid; i < TILEQ; i += 256) {
                dB[i]         = sH[i];
                dB[TILEQ + i] = sL[i];
            }
            if (tid < TN)
                reinterpret_cast<float*>(smem + SM_CN)[tid] =
                    g_x2[b * NP + tt * TN + tid];
        }
        __syncthreads();

        // ---- Phase A: MMA + fold + store, one n-half (64 cols) at a time ----
#pragma unroll 1
        for (int h = 0; h < 2; ++h) {
            float* distf = reinterpret_cast<float*>(smem + (h ? SM_D1 : SM_D0));
            float acc[8][4];
#pragma unroll
            for (int nt = 0; nt < 8; ++nt)
#pragma unroll
                for (int e = 0; e < 4; ++e) acc[nt][e] = 0.f;

#pragma unroll
            for (int np = 0; np < 4; ++np) {
#pragma unroll
                for (int k = 0; k < 4; ++k) {
                    uint32_t Bh[4], Bl[4];
                    uint32_t ba = sb + SM_BH + b_lane_off +
                                  (uint32_t)((h * 64 + np * 16) * PITCHB) +
                                  (uint32_t)(k * 32);
                    ldsm4(Bh, ba);
                    ldsm4(Bl, ba + (SM_BL - SM_BH));
                    mma16816(acc[2 * np],     Ah[k], Bh + 0);
                    mma16816(acc[2 * np],     Ah[k], Bl + 0);
                    mma16816(acc[2 * np],     Al[k], Bh + 0);
                    mma16816(acc[2 * np + 1], Ah[k], Bh + 2);
                    mma16816(acc[2 * np + 1], Ah[k], Bl + 2);
                    mma16816(acc[2 * np + 1], Al[k], Bh + 2);
                }
            }
#pragma unroll
            for (int nt = 0; nt < 8; ++nt) {
                const int c0 = nt * 8 + tg * 2;
                float2 cnp = *reinterpret_cast<const float2*>(cn + h * 64 + c0);
                float2 d0, d1;
                d0.x = fmaf(-2.f, acc[nt][0], qn0 + cnp.x);
                d0.y = fmaf(-2.f, acc[nt][1], qn0 + cnp.y);
                d1.x = fmaf(-2.f, acc[nt][2], qn1 + cnp.x);
                d1.y = fmaf(-2.f, acc[nt][3], qn1 + cnp.y);
                *reinterpret_cast<float2*>(distf + (size_t)row0 * DPITCH + c0) = d0;
                *reinterpret_cast<float2*>(distf + (size_t)(row0 + 8) * DPITCH + c0) = d1;
            }
        }
        __syncthreads();  // both dist halves ready

        // ---- Phase B: branchless pass-mask, then compact insert loop ----
#pragma unroll 1
        for (int h = 0; h < 2; ++h) {
            const float* rowf = reinterpret_cast<float*>(
                smem + (h ? SM_D1 : SM_D0)) + (size_t)srow * DPITCH + shb * 32;
            const float4* drow = reinterpret_cast<const float4*>(rowf);
            const int base = tt * TN + h * 64 + shb * 32;
            const float thr = dk[KNN - 1];  // stale gate: superset, re-gated below
            uint32_t mask = 0;
#pragma unroll
            for (int j4 = 0; j4 < 8; ++j4) {
                float4 v = drow[j4];
                uint32_t m = (uint32_t)(v.x < thr)
                           | ((uint32_t)(v.y < thr) << 1)
                           | ((uint32_t)(v.z < thr) << 2)
                           | ((uint32_t)(v.w < thr) << 3);
                mask |= m << (4 * j4);
            }
#pragma unroll 1
            while (mask) {
                int j = __ffs(mask) - 1;
                mask &= mask - 1;
                float d = rowf[j];
                INSERTF(d, base + j);
            }
        }
    }

    // ---- merge the 2 per-row lists via packed u64 ord-keys ----
    __syncthreads();
    unsigned long long* keys = reinterpret_cast<unsigned long long*>(smem);
#pragma unroll
    for (int k = 0; k < KNN; ++k) {
        uint32_t u = __float_as_uint(dk[k]);
        u ^= (uint32_t)((int)u >> 31) | 0x80000000u;
        keys[((size_t)srow * 2 + shb) * KNN + k] =
            ((unsigned long long)u << 32) | (uint32_t)ik[k];
    }
    __syncthreads();

    if (tid < TM) {
        const int r   = tid;
        const int gqi = b * NP + qbase + r;
        const unsigned long long* L = keys + (size_t)r * 2 * KNN;
        float* od   = out + (size_t)gqi * KNN;
        float* odst = out + OUTBLK + (size_t)gqi * KNN;
        float* osrc = out + 2 * OUTBLK + (size_t)gqi * KNN;
        const float fsrc = (float)gqi;
        int i0 = 0, i1 = 0;
#pragma unroll 1
        for (int k = 0; k < KNN; ++k) {
            unsigned long long h0 = (i0 < KNN) ? L[i0] : ~0ull;
            unsigned long long h1 = (i1 < KNN) ? L[KNN + i1] : ~0ull;
            unsigned long long m;
            if (h0 <= h1) { m = h0; ++i0; } else { m = h1; ++i1; }
            uint32_t o = (uint32_t)(m >> 32);
            uint32_t msk = (o & 0x80000000u) ? 0x80000000u : 0xFFFFFFFFu;
            od[k] = __uint_as_float(o ^ msk);
            if (write_edges) {
                odst[k] = (float)((uint32_t)(m & 0xFFFFFFFFu) + b * NP);
                osrc[k] = fsrc;
            }
        }
    }
}

extern "C" void kernel_launch(void* const* d_in, const int* in_sizes, int n_in,
                              void* d_out, int out_size) {
    const float* h   = (const float*)d_in[0];
    float*       out = (float*)d_out;
    const int write_edges = (out_size >= 3 * OUTBLK) ? 1 : 0;

    cudaFuncSetAttribute(knn_kernel, cudaFuncAttributeMaxDynamicSharedMemorySize,
                         SM_TOT);

    prep_kernel<<<(NS * NP) / 256, 256>>>(h);
    dim3 grid(NP / TM, NS);
    knn_kernel<<<grid, 256, SM_TOT>>>(out, write_edges);
}

// round 15
// speedup vs baseline: 2.4199x; 1.1254x over previous
#include <cuda_runtime.h>
#include <cuda_fp16.h>
#include <cstdint>

// NearestNeighborGraph: 16 samples x 2048 points x 64 dims, K=16.
// Output (float32): [knn_dist | dst | src], each 16*2048*16.
//
// fp16 2-term-split mma.sync Gram tiles; distances staged in two SMEM
// half-buffers; selection = branchless pass-mask + compact ffs insert loop.
// Pipeline: 2 barriers/tile; cp.async B(t+1) copy overlapped with scan(t).
// 2 CTAs/SM.

#define NS     16
#define NP     2048
#define DIMS   64
#define KNN    16
#define TM     128
#define TN     128
#define NTILES (NP / TN)
#define OUTBLK (NS * NP * KNN)

#define PITCHB 144           // A/B smem row pitch bytes (9x16B, ldmatrix conflict-free)
#define PITCHQ 9             // uint4 per row
#define TILEQ  (TM * PITCHQ) // 1152 uint4 = 18432 B per term tile
#define DPITCH 68            // dist half-tile row pitch in floats (64+4)

// SMEM layout (bytes). A staged in B region pre-loop (dead after frag load).
#define SM_B   0
#define SM_BH  0
#define SM_BL  18432
#define SM_D0  36864
#define SM_D1  (SM_D0 + TM * DPITCH * 4)   // 71680
#define SM_CN  (SM_D1 + TM * DPITCH * 4)   // 106496
#define SM_TOT (SM_CN + 512)               // 107008

__device__ uint4 g_h16[NS * NP * PITCHQ];  // fp16 hi plane, 144B pitch
__device__ uint4 g_l16[NS * NP * PITCHQ];  // fp16 lo plane
__device__ float g_x2[NS * NP];            // fp32 norms

// ---------------- helpers ----------------
__device__ __forceinline__ uint32_t smem_u32(const void* p) {
    uint32_t a;
    asm("{ .reg .u64 t; cvta.to.shared.u64 t, %1; cvt.u32.u64 %0, t; }"
        : "=r"(a) : "l"(p));
    return a;
}

__device__ __forceinline__ void ldsm4(uint32_t* r, uint32_t addr) {
    asm volatile("ldmatrix.sync.aligned.m8n8.x4.shared.b16 {%0,%1,%2,%3}, [%4];"
                 : "=r"(r[0]), "=r"(r[1]), "=r"(r[2]), "=r"(r[3]) : "r"(addr));
}

__device__ __forceinline__ void mma16816(float* d, const uint32_t* a,
                                         const uint32_t* b) {
    asm volatile(
        "mma.sync.aligned.m16n8k16.row.col.f32.f16.f16.f32 "
        "{%0,%1,%2,%3}, {%4,%5,%6,%7}, {%8,%9}, {%0,%1,%2,%3};"
        : "+f"(d[0]), "+f"(d[1]), "+f"(d[2]), "+f"(d[3])
        : "r"(a[0]), "r"(a[1]), "r"(a[2]), "r"(a[3]), "r"(b[0]), "r"(b[1]));
}

__device__ __forceinline__ void cp16(uint32_t saddr, const void* gaddr) {
    asm volatile("cp.async.cg.shared.global [%0], [%1], 16;"
                 :: "r"(saddr), "l"(gaddr));
}
__device__ __forceinline__ void cp4(uint32_t saddr, const void* gaddr) {
    asm volatile("cp.async.ca.shared.global [%0], [%1], 4;"
                 :: "r"(saddr), "l"(gaddr));
}
#define CP_COMMIT() asm volatile("cp.async.commit_group;" ::: "memory")
#define CP_WAIT0()  asm volatile("cp.async.wait_group 0;" ::: "memory")

__device__ __forceinline__ uint32_t pack_h2(__half lo, __half hi) {
    __half2 h = __halves2half2(lo, hi);
    return *reinterpret_cast<uint32_t*>(&h);
}

// Float sorted insert; strict '<' + ascending idx processing order => stable
// ties toward the smaller index (lax.top_k semantics).
#define INSERTF(dval, idx) do {                                                \
    if ((dval) < dk[KNN - 1]) {                                                \
        dk[KNN - 1] = (dval);                                                  \
        ik[KNN - 1] = (idx);                                                   \
        _Pragma("unroll")                                                      \
        for (int _t = KNN - 1; _t > 0; --_t) {                                 \
            if (dk[_t] < dk[_t - 1]) {                                         \
                float _fd = dk[_t]; dk[_t] = dk[_t - 1]; dk[_t - 1] = _fd;     \
                int   _fi = ik[_t]; ik[_t] = ik[_t - 1]; ik[_t - 1] = _fi;     \
            }                                                                  \
        }                                                                      \
    }                                                                          \
} while (0)

// ---------------- prologue: fp16 split planes + norms ----------------
__global__ void __launch_bounds__(256) prep_kernel(const float* __restrict__ h) {
    int r = blockIdx.x * blockDim.x + threadIdx.x;
    if (r >= NS * NP) return;
    const float4* src = reinterpret_cast<const float4*>(h + (size_t)r * DIMS);
    float s = 0.f;
#pragma unroll
    for (int q = 0; q < 8; ++q) {
        float4 x0 = src[2 * q];
        float4 x1 = src[2 * q + 1];
        float f[8] = {x0.x, x0.y, x0.z, x0.w, x1.x, x1.y, x1.z, x1.w};
        uint32_t rh[4], rl[4];
#pragma unroll
        for (int e = 0; e < 4; ++e) {
            float a = f[2 * e], c = f[2 * e + 1];
            __half ah = __float2half_rn(a), ch = __float2half_rn(c);
            float al = a - __half2float(ah);
            float cl = c - __half2float(ch);
            rh[e] = pack_h2(ah, ch);
            rl[e] = pack_h2(__float2half_rn(al), __float2half_rn(cl));
            s += a * a;
            s += c * c;
        }
        g_h16[(size_t)r * PITCHQ + q] = make_uint4(rh[0], rh[1], rh[2], rh[3]);
        g_l16[(size_t)r * PITCHQ + q] = make_uint4(rl[0], rl[1], rl[2], rl[3]);
    }
    g_h16[(size_t)r * PITCHQ + 8] = make_uint4(0, 0, 0, 0);
    g_l16[(size_t)r * PITCHQ + 8] = make_uint4(0, 0, 0, 0);
    g_x2[r] = s;
}

// ---------------- main kernel ----------------
__global__ void __launch_bounds__(256, 2) knn_kernel(float* __restrict__ out,
                                                     int write_edges) {
    extern __shared__ char smem[];
    const uint32_t sb = smem_u32(smem);
    const int tid  = threadIdx.x;
    const int w    = tid >> 5;
    const int lane = tid & 31;
    const int tg   = lane & 3;
    const int g    = lane >> 2;
    const int b    = blockIdx.y;
    const int qbase = blockIdx.x * TM;

    // ---- stage A (query) tiles into the B region (dead after frag load) ----
    {
        const uint4* srcH = g_h16 + (size_t)(b * NP + qbase) * PITCHQ;
        const uint4* srcL = g_l16 + (size_t)(b * NP + qbase) * PITCHQ;
        uint4* dA = reinterpret_cast<uint4*>(smem + SM_B);
        for (int i = tid; i < TILEQ; i += 256) {
            dA[i]         = srcH[i];
            dA[TILEQ + i] = srcL[i];
        }
    }
    __syncthreads();

    // ---- cache A fragments (fixed for whole CTA) ----
    uint32_t Ah[4][4], Al[4][4];
    {
        uint32_t a_off = sb + SM_BH + (uint32_t)(w * 16 + (lane & 15)) * PITCHB +
                         (uint32_t)(lane >> 4) * 16;
#pragma unroll
        for (int k = 0; k < 4; ++k) {
            ldsm4(Ah[k], a_off + k * 32);
            ldsm4(Al[k], a_off + (SM_BL - SM_BH) + k * 32);
        }
    }
    const int row0 = w * 16 + g;
    const float qn0 = g_x2[b * NP + qbase + row0];
    const float qn1 = g_x2[b * NP + qbase + row0 + 8];

    // ---- scan thread state: half a row each ----
    const int srow = tid >> 1;
    const int shb  = tid & 1;
    float dk[KNN];
    int   ik[KNN];
#pragma unroll
    for (int k = 0; k < KNN; ++k) { dk[k] = 3.4e38f; ik[k] = 0; }

    const uint32_t b_lane_off =
        (uint32_t)(((lane & 7) + ((lane >> 4) << 3)) * PITCHB) +
        ((lane & 8) ? 16u : 0u);
    const float* cn = reinterpret_cast<const float*>(smem + SM_CN);

    __syncthreads();  // A-frag ldsm reads done -> B region writable

    // ---- preload tile 0 (cp.async, direct to SMEM) ----
    {
        const uint4* sH = g_h16 + (size_t)(b * NP) * PITCHQ;
        const uint4* sL = g_l16 + (size_t)(b * NP) * PITCHQ;
        for (int i = tid; i < TILEQ; i += 256) {
            cp16(sb + SM_B + i * 16,                sH + i);
            cp16(sb + SM_B + TILEQ * 16 + i * 16,   sL + i);
        }
        if (tid < TN) cp4(sb + SM_CN + tid * 4, g_x2 + b * NP + tid);
        CP_COMMIT();
        CP_WAIT0();
    }
    __syncthreads();  // tile 0 visible to all

    for (int tt = 0; tt < NTILES; ++tt) {
        // ---- Phase A: MMA + fold + store, one n-half (64 cols) at a time ----
#pragma unroll 1
        for (int h = 0; h < 2; ++h) {
            float* distf = reinterpret_cast<float*>(smem + (h ? SM_D1 : SM_D0));
            float acc[8][4];
#pragma unroll
            for (int nt = 0; nt < 8; ++nt)
#pragma unroll
                for (int e = 0; e < 4; ++e) acc[nt][e] = 0.f;

#pragma unroll
            for (int np = 0; np < 4; ++np) {
#pragma unroll
                for (int k = 0; k < 4; ++k) {
                    uint32_t Bh[4], Bl[4];
                    uint32_t ba = sb + SM_BH + b_lane_off +
                                  (uint32_t)((h * 64 + np * 16) * PITCHB) +
                                  (uint32_t)(k * 32);
                    ldsm4(Bh, ba);
                    ldsm4(Bl, ba + (SM_BL - SM_BH));
                    mma16816(acc[2 * np],     Ah[k], Bh + 0);
                    mma16816(acc[2 * np],     Ah[k], Bl + 0);
                    mma16816(acc[2 * np],     Al[k], Bh + 0);
                    mma16816(acc[2 * np + 1], Ah[k], Bh + 2);
                    mma16816(acc[2 * np + 1], Ah[k], Bl + 2);
                    mma16816(acc[2 * np + 1], Al[k], Bh + 2);
                }
            }
#pragma unroll
            for (int nt = 0; nt < 8; ++nt) {
                const int c0 = nt * 8 + tg * 2;
                float2 cnp = *reinterpret_cast<const float2*>(cn + h * 64 + c0);
                float2 d0, d1;
                d0.x = fmaf(-2.f, acc[nt][0], qn0 + cnp.x);
                d0.y = fmaf(-2.f, acc[nt][1], qn0 + cnp.y);
                d1.x = fmaf(-2.f, acc[nt][2], qn1 + cnp.x);
                d1.y = fmaf(-2.f, acc[nt][3], qn1 + cnp.y);
                *reinterpret_cast<float2*>(distf + (size_t)row0 * DPITCH + c0) = d0;
                *reinterpret_cast<float2*>(distf + (size_t)(row0 + 8) * DPITCH + c0) = d1;
            }
        }
        __syncthreads();  // D ready; all B/cn reads of tile tt done

        // ---- issue prefetch of tile tt+1 (overlaps the scan below) ----
        if (tt + 1 < NTILES) {
            const uint4* sH = g_h16 + (size_t)(b * NP + (tt + 1) * TN) * PITCHQ;
            const uint4* sL = g_l16 + (size_t)(b * NP + (tt + 1) * TN) * PITCHQ;
            for (int i = tid; i < TILEQ; i += 256) {
                cp16(sb + SM_B + i * 16,              sH + i);
                cp16(sb + SM_B + TILEQ * 16 + i * 16, sL + i);
            }
            if (tid < TN)
                cp4(sb + SM_CN + tid * 4, g_x2 + b * NP + (tt + 1) * TN + tid);
        }
        CP_COMMIT();

        // ---- Phase B: branchless pass-mask, then compact insert loop ----
#pragma unroll 1
        for (int h = 0; h < 2; ++h) {
            const float* rowf = reinterpret_cast<float*>(
                smem + (h ? SM_D1 : SM_D0)) + (size_t)srow * DPITCH + shb * 32;
            const float4* drow = reinterpret_cast<const float4*>(rowf);
            const int base = tt * TN + h * 64 + shb * 32;
            const float thr = dk[KNN - 1];  // stale gate: superset, re-gated below
            uint32_t mask = 0;
#pragma unroll
            for (int j4 = 0; j4 < 8; ++j4) {
                float4 v = drow[j4];
                uint32_t m = (uint32_t)(v.x < thr)
                           | ((uint32_t)(v.y < thr) << 1)
                           | ((uint32_t)(v.z < thr) << 2)
                           | ((uint32_t)(v.w < thr) << 3);
                mask |= m << (4 * j4);
            }
#pragma unroll 1
            while (mask) {
                int j = __ffs(mask) - 1;
                mask &= mask - 1;
                float d = rowf[j];
                INSERTF(d, base + j);
            }
        }

        CP_WAIT0();       // own cp.async groups landed
        __syncthreads();  // all threads' copies landed; D free; B(t+1) visible
    }

    // ---- merge the 2 per-row lists via packed u64 ord-keys ----
    unsigned long long* keys = reinterpret_cast<unsigned long long*>(smem);
#pragma unroll
    for (int k = 0; k < KNN; ++k) {
        uint32_t u = __float_as_uint(dk[k]);
        u ^= (uint32_t)((int)u >> 31) | 0x80000000u;
        keys[((size_t)srow * 2 + shb) * KNN + k] =
            ((unsigned long long)u << 32) | (uint32_t)ik[k];
    }
    __syncthreads();

    if (tid < TM) {
        const int r   = tid;
        const int gqi = b * NP + qbase + r;
        const unsigned long long* L = keys + (size_t)r * 2 * KNN;
        float* od   = out + (size_t)gqi * KNN;
        float* odst = out + OUTBLK + (size_t)gqi * KNN;
        float* osrc = out + 2 * OUTBLK + (size_t)gqi * KNN;
        const float fsrc = (float)gqi;
        int i0 = 0, i1 = 0;
#pragma unroll 1
        for (int k = 0; k < KNN; ++k) {
            unsigned long long h0 = (i0 < KNN) ? L[i0] : ~0ull;
            unsigned long long h1 = (i1 < KNN) ? L[KNN + i1] : ~0ull;
            unsigned long long m;
            if (h0 <= h1) { m = h0; ++i0; } else { m = h1; ++i1; }
            uint32_t o = (uint32_t)(m >> 32);
            uint32_t msk = (o & 0x80000000u) ? 0x80000000u : 0xFFFFFFFFu;
            od[k] = __uint_as_float(o ^ msk);
            if (write_edges) {
                odst[k] = (float)((uint32_t)(m & 0xFFFFFFFFu) + b * NP);
                osrc[k] = fsrc;
            }
        }
    }
}

extern "C" void kernel_launch(void* const* d_in, const int* in_sizes, int n_in,
                              void* d_out, int out_size) {
    const float* h   = (const float*)d_in[0];
    float*       out = (float*)d_out;
    const int write_edges = (out_size >= 3 * OUTBLK) ? 1 : 0;

    cudaFuncSetAttribute(knn_kernel, cudaFuncAttributeMaxDynamicSharedMemorySize,
                         SM_TOT);

    prep_kernel<<<(NS * NP) / 256, 256>>>(h);
    dim3 grid(NP / TM, NS);
    knn_kernel<<<grid, 256, SM_TOT>>>(out, write_edges);
}

// round 16
// speedup vs baseline: 2.4261x; 1.0026x over previous
#include <cuda_runtime.h>
#include <cuda_fp16.h>
#include <cstdint>

// NearestNeighborGraph: 16 samples x 2048 points x 64 dims, K=16.
// Output (float32): [knn_dist | dst | src], each 16*2048*16.
//
// fp16 2-term-split mma.sync Gram tiles (k-outer loop for tensor ILP);
// distances staged in two SMEM half-buffers; selection = branchless pass-mask
// gated by a shared per-row threshold (min of both row-threads' 16th) +
// compact ffs insert loop. cp.async B(t+1) overlapped with scan(t). 2 CTAs/SM.

#define NS     16
#define NP     2048
#define DIMS   64
#define KNN    16
#define TM     128
#define TN     128
#define NTILES (NP / TN)
#define OUTBLK (NS * NP * KNN)

#define PITCHB 144           // A/B smem row pitch bytes (9x16B, ldmatrix conflict-free)
#define PITCHQ 9             // uint4 per row
#define TILEQ  (TM * PITCHQ) // 1152 uint4 = 18432 B per term tile
#define DPITCH 68            // dist half-tile row pitch in floats (64+4)

// SMEM layout (bytes). A staged in B region pre-loop (dead after frag load).
#define SM_B   0
#define SM_BH  0
#define SM_BL  18432
#define SM_D0  36864
#define SM_D1  (SM_D0 + TM * DPITCH * 4)   // 71680
#define SM_CN  (SM_D1 + TM * DPITCH * 4)   // 106496
#define SM_THR (SM_CN + 512)               // 256 floats = 1024 B
#define SM_TOT (SM_THR + 1024)             // 108032

__device__ uint4 g_h16[NS * NP * PITCHQ];  // fp16 hi plane, 144B pitch
__device__ uint4 g_l16[NS * NP * PITCHQ];  // fp16 lo plane
__device__ float g_x2[NS * NP];            // fp32 norms

// ---------------- helpers ----------------
__device__ __forceinline__ uint32_t smem_u32(const void* p) {
    uint32_t a;
    asm("{ .reg .u64 t; cvta.to.shared.u64 t, %1; cvt.u32.u64 %0, t; }"
        : "=r"(a) : "l"(p));
    return a;
}

__device__ __forceinline__ void ldsm4(uint32_t* r, uint32_t addr) {
    asm volatile("ldmatrix.sync.aligned.m8n8.x4.shared.b16 {%0,%1,%2,%3}, [%4];"
                 : "=r"(r[0]), "=r"(r[1]), "=r"(r[2]), "=r"(r[3]) : "r"(addr));
}

__device__ __forceinline__ void mma16816(float* d, const uint32_t* a,
                                         const uint32_t* b) {
    asm volatile(
        "mma.sync.aligned.m16n8k16.row.col.f32.f16.f16.f32 "
        "{%0,%1,%2,%3}, {%4,%5,%6,%7}, {%8,%9}, {%0,%1,%2,%3};"
        : "+f"(d[0]), "+f"(d[1]), "+f"(d[2]), "+f"(d[3])
        : "r"(a[0]), "r"(a[1]), "r"(a[2]), "r"(a[3]), "r"(b[0]), "r"(b[1]));
}

__device__ __forceinline__ void cp16(uint32_t saddr, const void* gaddr) {
    asm volatile("cp.async.cg.shared.global [%0], [%1], 16;"
                 :: "r"(saddr), "l"(gaddr));
}
__device__ __forceinline__ void cp4(uint32_t saddr, const void* gaddr) {
    asm volatile("cp.async.ca.shared.global [%0], [%1], 4;"
                 :: "r"(saddr), "l"(gaddr));
}
#define CP_COMMIT() asm volatile("cp.async.commit_group;" ::: "memory")
#define CP_WAIT0()  asm volatile("cp.async.wait_group 0;" ::: "memory")

__device__ __forceinline__ uint32_t pack_h2(__half lo, __half hi) {
    __half2 h = __halves2half2(lo, hi);
    return *reinterpret_cast<uint32_t*>(&h);
}

// Float sorted insert; strict '<' + ascending idx processing order => stable
// ties toward the smaller index (lax.top_k semantics).
#define INSERTF(dval, idx) do {                                                \
    if ((dval) < dk[KNN - 1]) {                                                \
        dk[KNN - 1] = (dval);                                                  \
        ik[KNN - 1] = (idx);                                                   \
        _Pragma("unroll")                                                      \
        for (int _t = KNN - 1; _t > 0; --_t) {                                 \
            if (dk[_t] < dk[_t - 1]) {                                         \
                float _fd = dk[_t]; dk[_t] = dk[_t - 1]; dk[_t - 1] = _fd;     \
                int   _fi = ik[_t]; ik[_t] = ik[_t - 1]; ik[_t - 1] = _fi;     \
            }                                                                  \
        }                                                                      \
    }                                                                          \
} while (0)

// ---------------- prologue: fp16 split planes + norms ----------------
__global__ void __launch_bounds__(256) prep_kernel(const float* __restrict__ h) {
    int r = blockIdx.x * blockDim.x + threadIdx.x;
    if (r >= NS * NP) return;
    const float4* src = reinterpret_cast<const float4*>(h + (size_t)r * DIMS);
    float s = 0.f;
#pragma unroll
    for (int q = 0; q < 8; ++q) {
        float4 x0 = src[2 * q];
        float4 x1 = src[2 * q + 1];
        float f[8] = {x0.x, x0.y, x0.z, x0.w, x1.x, x1.y, x1.z, x1.w};
        uint32_t rh[4], rl[4];
#pragma unroll
        for (int e = 0; e < 4; ++e) {
            float a = f[2 * e], c = f[2 * e + 1];
            __half ah = __float2half_rn(a), ch = __float2half_rn(c);
            float al = a - __half2float(ah);
            float cl = c - __half2float(ch);
            rh[e] = pack_h2(ah, ch);
            rl[e] = pack_h2(__float2half_rn(al), __float2half_rn(cl));
            s += a * a;
            s += c * c;
        }
        g_h16[(size_t)r * PITCHQ + q] = make_uint4(rh[0], rh[1], rh[2], rh[3]);
        g_l16[(size_t)r * PITCHQ + q] = make_uint4(rl[0], rl[1], rl[2], rl[3]);
    }
    g_h16[(size_t)r * PITCHQ + 8] = make_uint4(0, 0, 0, 0);
    g_l16[(size_t)r * PITCHQ + 8] = make_uint4(0, 0, 0, 0);
    g_x2[r] = s;
}

// ---------------- main kernel ----------------
__global__ void __launch_bounds__(256, 2) knn_kernel(float* __restrict__ out,
                                                     int write_edges) {
    extern __shared__ char smem[];
    const uint32_t sb = smem_u32(smem);
    const int tid  = threadIdx.x;
    const int w    = tid >> 5;
    const int lane = tid & 31;
    const int tg   = lane & 3;
    const int g    = lane >> 2;
    const int b    = blockIdx.y;
    const int qbase = blockIdx.x * TM;

    // ---- stage A (query) tiles into the B region (dead after frag load) ----
    {
        const uint4* srcH = g_h16 + (size_t)(b * NP + qbase) * PITCHQ;
        const uint4* srcL = g_l16 + (size_t)(b * NP + qbase) * PITCHQ;
        uint4* dA = reinterpret_cast<uint4*>(smem + SM_B);
        for (int i = tid; i < TILEQ; i += 256) {
            dA[i]         = srcH[i];
            dA[TILEQ + i] = srcL[i];
        }
    }
    __syncthreads();

    // ---- cache A fragments (fixed for whole CTA) ----
    uint32_t Ah[4][4], Al[4][4];
    {
        uint32_t a_off = sb + SM_BH + (uint32_t)(w * 16 + (lane & 15)) * PITCHB +
                         (uint32_t)(lane >> 4) * 16;
#pragma unroll
        for (int k = 0; k < 4; ++k) {
            ldsm4(Ah[k], a_off + k * 32);
            ldsm4(Al[k], a_off + (SM_BL - SM_BH) + k * 32);
        }
    }
    const int row0 = w * 16 + g;
    const float qn0 = g_x2[b * NP + qbase + row0];
    const float qn1 = g_x2[b * NP + qbase + row0 + 8];

    // ---- scan thread state: half a row each ----
    const int srow = tid >> 1;
    const int shb  = tid & 1;
    float dk[KNN];
    int   ik[KNN];
#pragma unroll
    for (int k = 0; k < KNN; ++k) { dk[k] = 3.4e38f; ik[k] = 0; }

    const uint32_t b_lane_off =
        (uint32_t)(((lane & 7) + ((lane >> 4) << 3)) * PITCHB) +
        ((lane & 8) ? 16u : 0u);
    const float* cn = reinterpret_cast<const float*>(smem + SM_CN);
    float* sthr = reinterpret_cast<float*>(smem + SM_THR);

    __syncthreads();  // A-frag ldsm reads done -> B region writable

    // ---- preload tile 0 (cp.async) + init shared thresholds ----
    {
        const uint4* sH = g_h16 + (size_t)(b * NP) * PITCHQ;
        const uint4* sL = g_l16 + (size_t)(b * NP) * PITCHQ;
        for (int i = tid; i < TILEQ; i += 256) {
            cp16(sb + SM_B + i * 16,                sH + i);
            cp16(sb + SM_B + TILEQ * 16 + i * 16,   sL + i);
        }
        if (tid < TN) cp4(sb + SM_CN + tid * 4, g_x2 + b * NP + tid);
        sthr[tid] = 3.4e38f;
        CP_COMMIT();
        CP_WAIT0();
    }
    __syncthreads();  // tile 0 + thresholds visible to all

    for (int tt = 0; tt < NTILES; ++tt) {
        // ---- Phase A: MMA + fold + store, one n-half (64 cols) at a time ----
#pragma unroll 1
        for (int h = 0; h < 2; ++h) {
            float* distf = reinterpret_cast<float*>(smem + (h ? SM_D1 : SM_D0));
            float acc[8][4];
#pragma unroll
            for (int nt = 0; nt < 8; ++nt)
#pragma unroll
                for (int e = 0; e < 4; ++e) acc[nt][e] = 0.f;

            // k outer, np inner: per-accumulator dependency distance = 8
            // tile-pairs (per-acc MMA order unchanged -> bit-identical).
#pragma unroll
            for (int k = 0; k < 4; ++k) {
#pragma unroll
                for (int np = 0; np < 4; ++np) {
                    uint32_t Bh[4], Bl[4];
                    uint32_t ba = sb + SM_BH + b_lane_off +
                                  (uint32_t)((h * 64 + np * 16) * PITCHB) +
                                  (uint32_t)(k * 32);
                    ldsm4(Bh, ba);
                    ldsm4(Bl, ba + (SM_BL - SM_BH));
                    mma16816(acc[2 * np],     Ah[k], Bh + 0);
                    mma16816(acc[2 * np],     Ah[k], Bl + 0);
                    mma16816(acc[2 * np],     Al[k], Bh + 0);
                    mma16816(acc[2 * np + 1], Ah[k], Bh + 2);
                    mma16816(acc[2 * np + 1], Ah[k], Bl + 2);
                    mma16816(acc[2 * np + 1], Al[k], Bh + 2);
                }
            }
#pragma unroll
            for (int nt = 0; nt < 8; ++nt) {
                const int c0 = nt * 8 + tg * 2;
                float2 cnp = *reinterpret_cast<const float2*>(cn + h * 64 + c0);
                float2 d0, d1;
                d0.x = fmaf(-2.f, acc[nt][0], qn0 + cnp.x);
                d0.y = fmaf(-2.f, acc[nt][1], qn0 + cnp.y);
                d1.x = fmaf(-2.f, acc[nt][2], qn1 + cnp.x);
                d1.y = fmaf(-2.f, acc[nt][3], qn1 + cnp.y);
                *reinterpret_cast<float2*>(distf + (size_t)row0 * DPITCH + c0) = d0;
                *reinterpret_cast<float2*>(distf + (size_t)(row0 + 8) * DPITCH + c0) = d1;
            }
        }
        __syncthreads();  // D ready; all B/cn reads of tile tt done

        // ---- issue prefetch of tile tt+1 (overlaps the scan below) ----
        if (tt + 1 < NTILES) {
            const uint4* sH = g_h16 + (size_t)(b * NP + (tt + 1) * TN) * PITCHQ;
            const uint4* sL = g_l16 + (size_t)(b * NP + (tt + 1) * TN) * PITCHQ;
            for (int i = tid; i < TILEQ; i += 256) {
                cp16(sb + SM_B + i * 16,              sH + i);
                cp16(sb + SM_B + TILEQ * 16 + i * 16, sL + i);
            }
            if (tid < TN)
                cp4(sb + SM_CN + tid * 4, g_x2 + b * NP + (tt + 1) * TN + tid);
        }
        CP_COMMIT();

        // ---- Phase B: shared-threshold pass-mask + compact insert loop ----
        // Gate = min(own 16th, partner's 16th from prev tile): always an upper
        // bound on the row's true 16th, so no final top-16 member is dropped;
        // INSERTF re-gates vs the local list (strict '<', ascending idx).
        const float pthr = sthr[tid ^ 1];
#pragma unroll 1
        for (int h = 0; h < 2; ++h) {
            const float* rowf = reinterpret_cast<float*>(
                smem + (h ? SM_D1 : SM_D0)) + (size_t)srow * DPITCH + shb * 32;
            const float4* drow = reinterpret_cast<const float4*>(rowf);
            const int base = tt * TN + h * 64 + shb * 32;
            const float thr = fminf(dk[KNN - 1], pthr);
            uint32_t mask = 0;
#pragma unroll
            for (int j4 = 0; j4 < 8; ++j4) {
                float4 v = drow[j4];
                uint32_t m = (uint32_t)(v.x < thr)
                           | ((uint32_t)(v.y < thr) << 1)
                           | ((uint32_t)(v.z < thr) << 2)
                           | ((uint32_t)(v.w < thr) << 3);
                mask |= m << (4 * j4);
            }
#pragma unroll 1
            while (mask) {
                int j = __ffs(mask) - 1;
                mask &= mask - 1;
                float d = rowf[j];
                INSERTF(d, base + j);
            }
        }
        sthr[tid] = dk[KNN - 1];  // publish for partner (read after barrier)

        CP_WAIT0();       // own cp.async groups landed
        __syncthreads();  // all copies landed; D free; B(t+1) + thr visible
    }

    // ---- merge the 2 per-row lists via packed u64 ord-keys ----
    unsigned long long* keys = reinterpret_cast<unsigned long long*>(smem);
#pragma unroll
    for (int k = 0; k < KNN; ++k) {
        uint32_t u = __float_as_uint(dk[k]);
        u ^= (uint32_t)((int)u >> 31) | 0x80000000u;
        keys[((size_t)srow * 2 + shb) * KNN + k] =
            ((unsigned long long)u << 32) | (uint32_t)ik[k];
    }
    __syncthreads();

    if (tid < TM) {
        const int r   = tid;
        const int gqi = b * NP + qbase + r;
        const unsigned long long* L = keys + (size_t)r * 2 * KNN;
        float* od   = out + (size_t)gqi * KNN;
        float* odst = out + OUTBLK + (size_t)gqi * KNN;
        float* osrc = out + 2 * OUTBLK + (size_t)gqi * KNN;
        const float fsrc = (float)gqi;
        int i0 = 0, i1 = 0;
#pragma unroll 1
        for (int k = 0; k < KNN; ++k) {
            unsigned long long h0 = (i0 < KNN) ? L[i0] : ~0ull;
            unsigned long long h1 = (i1 < KNN) ? L[KNN + i1] : ~0ull;
            unsigned long long m;
            if (h0 <= h1) { m = h0; ++i0; } else { m = h1; ++i1; }
            uint32_t o = (uint32_t)(m >> 32);
            uint32_t msk = (o & 0x80000000u) ? 0x80000000u : 0xFFFFFFFFu;
            od[k] = __uint_as_float(o ^ msk);
            if (write_edges) {
                odst[k] = (float)((uint32_t)(m & 0xFFFFFFFFu) + b * NP);
                osrc[k] = fsrc;
            }
        }
    }
}

extern "C" void kernel_launch(void* const* d_in, const int* in_sizes, int n_in,
                              void* d_out, int out_size) {
    const float* h   = (const float*)d_in[0];
    float*       out = (float*)d_out;
    const int write_edges = (out_size >= 3 * OUTBLK) ? 1 : 0;

    cudaFuncSetAttribute(knn_kernel, cudaFuncAttributeMaxDynamicSharedMemorySize,
                         SM_TOT);

    prep_kernel<<<(NS * NP) / 256, 256>>>(h);
    dim3 grid(NP / TM, NS);
    knn_kernel<<<grid, 256, SM_TOT>>>(out, write_edges);
}